// round 15
// baseline (speedup 1.0000x reference)
#include <cuda_runtime.h>
#include <math.h>

// Problem constants
#define C_DIM 320
#define NPTS  2048
#define NWAY  2
#define KSHOT 5
#define KP    100
#define NCLS  3
#define NQ    2
#define MFG   (KSHOT*NPTS)           // 10240
#define MBG   (NWAY*KSHOT*NPTS)      // 20480
#define SHOT_STRIDE (C_DIM*NPTS)     // 655360
#define TJM   10                     // seeds per tile
#define PTS   4                      // points per thread
#define NPROT (NCLS*KP)              // 300
#define MQ    (NQ*NPTS)              // 4096

typedef unsigned long long ull;

// Scratch (device globals — no allocation allowed)
__device__ int    g_seed_idx[NPROT];
__device__ int    g_cidx[3*MBG];
__device__ int    g_ccnt[3];
__device__ __align__(16) float g_seeds [NPROT*C_DIM];
__device__ float  g_num   [NPROT*C_DIM];
__device__ float  g_cnt   [NPROT];
__device__ __align__(16) float g_protos[NPROT*C_DIM];
__device__ ull    g_akey  [3*MBG];
__device__ unsigned int g_qkey[MQ*NCLS];
__device__ float  g_qinv  [MQ];

// ---- monotonic float <-> uint key encoding ----
__device__ __forceinline__ unsigned fkey(float v) {
    unsigned u = __float_as_uint(v);
    return (u & 0x80000000u) ? ~u : (u | 0x80000000u);
}
__device__ __forceinline__ float fdec(unsigned k) {
    unsigned u = (k & 0x80000000u) ? (k ^ 0x80000000u) : ~k;
    return __uint_as_float(u);
}

// ---- packed f32x2 ops (full-rate fp32 on sm_103a) ----
__device__ __forceinline__ void fma2(ull& d, ull a, ull b) {
    asm("fma.rn.f32x2 %0, %1, %2, %0;" : "+l"(d) : "l"(a), "l"(b));
}
__device__ __forceinline__ ull pack2(float lo, float hi) {
    ull r; asm("mov.b64 %0, {%1, %2};" : "=l"(r) : "f"(lo), "f"(hi)); return r;
}
__device__ __forceinline__ float unpack_sum(ull a) {
    float lo = __uint_as_float((unsigned)a);
    float hi = __uint_as_float((unsigned)(a >> 32));
    return lo + hi;
}

// load 8 strided channels and pack into 4 f32x2 regs
__device__ __forceinline__ void load8(const float* __restrict__ fb, int cc, ull* r) {
    float f0 = fb[(cc+0)*NPTS], f1 = fb[(cc+1)*NPTS];
    float f2 = fb[(cc+2)*NPTS], f3 = fb[(cc+3)*NPTS];
    float f4 = fb[(cc+4)*NPTS], f5 = fb[(cc+5)*NPTS];
    float f6 = fb[(cc+6)*NPTS], f7 = fb[(cc+7)*NPTS];
    r[0] = pack2(f0, f1); r[1] = pack2(f2, f3);
    r[2] = pack2(f4, f5); r[3] = pack2(f6, f7);
}

// ---------------------------------------------------------------- zero scratch
__global__ void k_zero() {
    int i = blockIdx.x * blockDim.x + threadIdx.x;
    if (i < NPROT*C_DIM) g_num[i]  = 0.f;
    if (i < NPROT)       g_cnt[i]  = 0.f;
    if (i < 3*MBG)       g_akey[i] = 0ull;
    if (i < MQ*NCLS)     g_qkey[i] = 0u;
    if (i < 3)           g_ccnt[i] = 0;
}

// ---------------- ordered seed scan: first KP masked indices per partition
__global__ void __launch_bounds__(256) k_seedscan(const int* __restrict__ sy) {
    int p = blockIdx.x;
    int M = (p == 2) ? MBG : MFG;
    __shared__ int wsum[8];
    __shared__ int sbase;
    int tid = threadIdx.x, lane = tid & 31, w = tid >> 5;
    if (tid == 0) sbase = 0;
    __syncthreads();
    for (int base = 0; base < M; base += 256) {
        int idx = base + tid;
        int b = 0;
        if (idx < M) b = (p == 2) ? (sy[idx] == 0) : (sy[p*MFG + idx] != 0);
        unsigned bal = __ballot_sync(0xFFFFFFFFu, b);
        int lp = __popc(bal & ((1u << lane) - 1u));
        if (lane == 0) wsum[w] = __popc(bal);
        __syncthreads();
        int off = 0;
        for (int i = 0; i < w; i++) off += wsum[i];
        int pos = sbase + off + lp;
        if (b && pos < KP) g_seed_idx[p*KP + pos] = idx;
        __syncthreads();
        if (tid == 0) { int t = 0; for (int i = 0; i < 8; i++) t += wsum[i]; sbase += t; }
        __syncthreads();
        if (sbase >= KP) break;
    }
}

// ------------- parallel unordered compaction (order irrelevant for matching)
__global__ void __launch_bounds__(256) k_compact(const int* __restrict__ sy) {
    int p = blockIdx.y;
    int M = (p == 2) ? MBG : MFG;
    int idx = blockIdx.x * 256 + threadIdx.x;
    int b = (idx < M) ? ((p == 2) ? (sy[idx] == 0) : (sy[p*MFG + idx] != 0)) : 0;
    unsigned bal = __ballot_sync(0xFFFFFFFFu, b);
    int lane = threadIdx.x & 31;
    int lp = __popc(bal & ((1u << lane) - 1u));
    int base = 0;
    if (lane == 0 && bal) base = atomicAdd(&g_ccnt[p], __popc(bal));
    base = __shfl_sync(0xFFFFFFFFu, base, 0);
    if (b) g_cidx[p*MBG + base + lp] = idx;
}

// ------------------------------------------------ gather + normalize seeds
__global__ void k_norm_seeds(const float* __restrict__ sf) {
    int g = blockIdx.x;              // 0..299
    int p = g / KP;
    int idx = g_seed_idx[g];
    int grp = (p == 2) ? (idx >> 11) : (p*KSHOT + (idx >> 11));
    const float* fb = sf + (size_t)grp*SHOT_STRIDE + (idx & 2047);
    int c = threadIdx.x;             // 320 threads
    float v = fb[c * NPTS];
    __shared__ float red[16];
    __shared__ float stot;
    float s = v * v;
    #pragma unroll
    for (int o = 16; o; o >>= 1) s += __shfl_down_sync(0xFFFFFFFFu, s, o);
    if ((c & 31) == 0) red[c >> 5] = s;
    __syncthreads();
    if (c == 0) { float t = 0.f; for (int i = 0; i < C_DIM/32; i++) t += red[i]; stot = t; }
    __syncthreads();
    g_seeds[g*C_DIM + c] = v / (sqrtf(stot) + 1e-8f);
}

// ---- match: 4 points/thread x 10-seed tile, register-tiled f32x2 GEMM
__global__ void __launch_bounds__(128, 4) k_match(const float* __restrict__ sf) {
    __shared__ __align__(16) float s[TJM*C_DIM];
    int p = blockIdx.z, t = blockIdx.y;
    int cnt = g_ccnt[p];
    int i0 = blockIdx.x * (128*PTS);
    if (i0 >= cnt) return;
    const float* sp = g_seeds + (size_t)(p*KP + t*TJM)*C_DIM;
    for (int i = threadIdx.x; i < TJM*C_DIM; i += 128) s[i] = sp[i];
    __syncthreads();

    const float* fbp[PTS];
    bool valid[PTS];
    int ipt[PTS];
    #pragma unroll
    for (int k = 0; k < PTS; k++) {
        int i = i0 + threadIdx.x + 128*k;
        valid[k] = (i < cnt);
        ipt[k] = i;
        int ii = valid[k] ? i : (cnt - 1);
        int idx = g_cidx[p*MBG + ii];
        int grp = (p == 2) ? (idx >> 11) : (p*KSHOT + (idx >> 11));
        fbp[k] = sf + (size_t)grp*SHOT_STRIDE + (idx & 2047);
    }

    ull acc[PTS][TJM];
    #pragma unroll
    for (int k = 0; k < PTS; k++)
        #pragma unroll
        for (int j = 0; j < TJM; j++) acc[k][j] = 0ull;

    for (int cc = 0; cc < C_DIM; cc += 8) {
        ull A[PTS][4];
        #pragma unroll
        for (int k = 0; k < PTS; k++) load8(fbp[k], cc, A[k]);
        #pragma unroll
        for (int j = 0; j < TJM; j++) {
            ulonglong2 s01 = *(const ulonglong2*)&s[j*C_DIM + cc];
            ulonglong2 s23 = *(const ulonglong2*)&s[j*C_DIM + cc + 4];
            #pragma unroll
            for (int k = 0; k < PTS; k++) {
                fma2(acc[k][j], A[k][0], s01.x);
                fma2(acc[k][j], A[k][1], s01.y);
                fma2(acc[k][j], A[k][2], s23.x);
                fma2(acc[k][j], A[k][3], s23.y);
            }
        }
    }

    #pragma unroll
    for (int k = 0; k < PTS; k++) {
        if (!valid[k]) continue;
        float best = unpack_sum(acc[k][0]); int bj = 0;
        #pragma unroll
        for (int j = 1; j < TJM; j++) {
            float d = unpack_sum(acc[k][j]);
            if (d > best) { best = d; bj = j; }
        }
        ull key = ((ull)fkey(best) << 32) | (ull)(0xFFFFFFFFu - (unsigned)(t*TJM + bj));
        atomicMax(&g_akey[p*MBG + ipt[k]], key);
    }
}

// ------------- accumulate cluster sums (4-way channel split for parallelism)
__global__ void __launch_bounds__(128) k_accum(const float* __restrict__ sf) {
    int p = blockIdx.z;
    int cslice = blockIdx.y;                  // 0..3, 80 channels each
    int cnt = g_ccnt[p];
    int i = blockIdx.x * 128 + threadIdx.x;
    if (i >= cnt) return;
    int idx = g_cidx[p*MBG + i];
    int grp = (p == 2) ? (idx >> 11) : (p*KSHOT + (idx >> 11));
    const float* fb = sf + (size_t)grp*SHOT_STRIDE + (idx & 2047);
    unsigned j = 0xFFFFFFFFu - (unsigned)(g_akey[p*MBG + i] & 0xFFFFFFFFull);
    int proto = p*KP + (int)j;
    if (cslice == 0) atomicAdd(&g_cnt[proto], 1.0f);
    float* dst = g_num + (size_t)proto*C_DIM;
    int c0 = cslice * 80;
    #pragma unroll 4
    for (int c = c0; c < c0 + 80; c++) atomicAdd(&dst[c], fb[c*NPTS]);
}

// ------------------------------------------------ finalize + normalize protos
__global__ void k_norm_protos() {
    int g = blockIdx.x;
    int c = threadIdx.x;             // 320 threads
    float den = g_cnt[g] + 1e-8f;
    float v = g_num[g*C_DIM + c] / den;
    __shared__ float red[16];
    __shared__ float stot;
    float s = v * v;
    #pragma unroll
    for (int o = 16; o; o >>= 1) s += __shfl_down_sync(0xFFFFFFFFu, s, o);
    if ((c & 31) == 0) red[c >> 5] = s;
    __syncthreads();
    if (c == 0) { float t = 0.f; for (int i = 0; i < C_DIM/32; i++) t += red[i]; stot = t; }
    __syncthreads();
    g_protos[g*C_DIM + c] = v / (sqrtf(stot) + 1e-8f);
}

// ---- query match: 4 points/thread x 10-proto tile + fused norm (t==0)
// proto groups: [0..99]=fg class 1, [100..199]=fg class 2, [200..299]=bg cls 0
__global__ void __launch_bounds__(128) k_qmatch(const float* __restrict__ qf) {
    __shared__ __align__(16) float s[TJM*C_DIM];
    int t = blockIdx.y;                       // 0..29
    int pg = t / (KP/TJM);
    int cls = (pg == 2) ? 0 : pg + 1;
    const float* sp = g_protos + (size_t)t*TJM*C_DIM;
    for (int i = threadIdx.x; i < TJM*C_DIM; i += 128) s[i] = sp[i];
    __syncthreads();

    int m0 = blockIdx.x * (128*PTS);
    const float* fbp[PTS];
    int mpt[PTS];
    #pragma unroll
    for (int k = 0; k < PTS; k++) {
        int m = m0 + threadIdx.x + 128*k;
        mpt[k] = m;
        int q = m >> 11, n = m & 2047;
        fbp[k] = qf + (size_t)q*SHOT_STRIDE + n;
    }

    ull acc[PTS][TJM];
    #pragma unroll
    for (int k = 0; k < PTS; k++)
        #pragma unroll
        for (int j = 0; j < TJM; j++) acc[k][j] = 0ull;
    ull q2p[PTS];
    #pragma unroll
    for (int k = 0; k < PTS; k++) q2p[k] = 0ull;
    bool do_norm = (t == 0);

    for (int cc = 0; cc < C_DIM; cc += 8) {
        ull A[PTS][4];
        #pragma unroll
        for (int k = 0; k < PTS; k++) load8(fbp[k], cc, A[k]);
        #pragma unroll
        for (int j = 0; j < TJM; j++) {
            ulonglong2 s01 = *(const ulonglong2*)&s[j*C_DIM + cc];
            ulonglong2 s23 = *(const ulonglong2*)&s[j*C_DIM + cc + 4];
            #pragma unroll
            for (int k = 0; k < PTS; k++) {
                fma2(acc[k][j], A[k][0], s01.x);
                fma2(acc[k][j], A[k][1], s01.y);
                fma2(acc[k][j], A[k][2], s23.x);
                fma2(acc[k][j], A[k][3], s23.y);
            }
        }
        if (do_norm) {
            #pragma unroll
            for (int k = 0; k < PTS; k++) {
                fma2(q2p[k], A[k][0], A[k][0]); fma2(q2p[k], A[k][1], A[k][1]);
                fma2(q2p[k], A[k][2], A[k][2]); fma2(q2p[k], A[k][3], A[k][3]);
            }
        }
    }
    #pragma unroll
    for (int k = 0; k < PTS; k++) {
        if (do_norm) {
            float q2 = unpack_sum(q2p[k]);
            g_qinv[mpt[k]] = 1.f / (sqrtf(q2) + 1e-8f);
        }
        float mx = unpack_sum(acc[k][0]);
        #pragma unroll
        for (int j = 1; j < TJM; j++) mx = fmaxf(mx, unpack_sum(acc[k][j]));
        atomicMax(&g_qkey[mpt[k]*NCLS + cls], fkey(mx));
    }
}

// ------------------- loss, query_pred out, mean-threshold, final labels
__global__ void __launch_bounds__(1024) k_finalize(const int* __restrict__ qy,
                                                   float* __restrict__ out) {
    __shared__ float sconf[MQ];
    __shared__ signed char sarg[MQ];
    __shared__ float red[1024];
    int tid = threadIdx.x;
    float lsum = 0.f, csum = 0.f;
    #pragma unroll
    for (int r = 0; r < MQ/1024; r++) {
        int m = tid + r*1024;
        int q = m >> 11, n = m & 2047;
        float inv = g_qinv[m];
        float p0 = fdec(g_qkey[m*NCLS + 0]) * inv;
        float p1 = fdec(g_qkey[m*NCLS + 1]) * inv;
        float p2 = fdec(g_qkey[m*NCLS + 2]) * inv;
        out[1 + (size_t)(q*NCLS + 0)*NPTS + n] = p0;
        out[1 + (size_t)(q*NCLS + 1)*NPTS + n] = p1;
        out[1 + (size_t)(q*NCLS + 2)*NPTS + n] = p2;
        float mx = p0; int a = 0;
        if (p1 > mx) { mx = p1; a = 1; }
        if (p2 > mx) { mx = p2; a = 2; }
        float lse = mx + logf(expf(p0 - mx) + expf(p1 - mx) + expf(p2 - mx));
        int lab = qy[m];
        float pl = (lab == 0) ? p0 : ((lab == 1) ? p1 : p2);
        lsum += lse - pl;
        sconf[m] = mx;
        sarg[m]  = (signed char)a;
        csum += mx;
    }
    red[tid] = lsum; __syncthreads();
    for (int o = 512; o; o >>= 1) { if (tid < o) red[tid] += red[tid + o]; __syncthreads(); }
    float tot_l = red[0];
    __syncthreads();
    red[tid] = csum; __syncthreads();
    for (int o = 512; o; o >>= 1) { if (tid < o) red[tid] += red[tid + o]; __syncthreads(); }
    float mean_c = red[0] / (float)MQ;
    if (tid == 0) out[0] = 2.f * tot_l / (float)MQ;
    #pragma unroll
    for (int r = 0; r < MQ/1024; r++) {
        int m = tid + r*1024;
        out[1 + (size_t)NQ*NCLS*NPTS + m] = (sconf[m] > mean_c) ? (float)sarg[m] : -1.f;
    }
}

// ---------------------------------------------------------------------- launch
extern "C" void kernel_launch(void* const* d_in, const int* in_sizes, int n_in,
                              void* d_out, int out_size) {
    const float* sf = (const float*)d_in[0];   // support_feat [2,5,320,2048]
    const float* qf = (const float*)d_in[1];   // query_feat   [2,320,2048]
    const int*   sy = (const int*)  d_in[2];   // support_y    [2,5,2048]
    const int*   qy = (const int*)  d_in[3];   // query_y      [2,2048]
    float* out = (float*)d_out;                // [1 + 12288 + 4096]

    k_zero<<<(NPROT*C_DIM + 255)/256, 256>>>();
    k_seedscan<<<3, 256>>>(sy);
    k_compact<<<dim3(MBG/256, 3), 256>>>(sy);
    k_norm_seeds<<<NPROT, C_DIM>>>(sf);
    k_match<<<dim3(MBG/(128*PTS), KP/TJM, 3), 128>>>(sf);
    k_accum<<<dim3(MBG/128, 4, 3), 128>>>(sf);
    k_norm_protos<<<NPROT, C_DIM>>>();
    k_qmatch<<<dim3(MQ/(128*PTS), NPROT/TJM), 128>>>(qf);
    k_finalize<<<1, 1024>>>(qy, out);
}

// round 16
// speedup vs baseline: 1.2842x; 1.2842x over previous
#include <cuda_runtime.h>
#include <math.h>

// Problem constants
#define C_DIM 320
#define NPTS  2048
#define NWAY  2
#define KSHOT 5
#define KP    100
#define NCLS  3
#define NQ    2
#define MFG   (KSHOT*NPTS)           // 10240
#define MBG   (NWAY*KSHOT*NPTS)      // 20480
#define SHOT_STRIDE (C_DIM*NPTS)     // 655360
#define TJM   10                     // seeds per tile
#define PTS   4                      // points per thread
#define NPROT (NCLS*KP)              // 300
#define MQ    (NQ*NPTS)              // 4096

typedef unsigned long long ull;

// Scratch (device globals — no allocation allowed)
__device__ int    g_seed_idx[NPROT];
__device__ int    g_cidx[3*MBG];
__device__ int    g_ccnt[3];
__device__ __align__(16) float g_seeds [NPROT*C_DIM];
__device__ float  g_num   [NPROT*C_DIM];
__device__ float  g_cnt   [NPROT];
__device__ __align__(16) float g_protos[NPROT*C_DIM];
__device__ ull    g_akey  [3*MBG];
__device__ unsigned int g_qkey[MQ*NCLS];
__device__ float  g_qinv  [MQ];

// ---- monotonic float <-> uint key encoding ----
__device__ __forceinline__ unsigned fkey(float v) {
    unsigned u = __float_as_uint(v);
    return (u & 0x80000000u) ? ~u : (u | 0x80000000u);
}
__device__ __forceinline__ float fdec(unsigned k) {
    unsigned u = (k & 0x80000000u) ? (k ^ 0x80000000u) : ~k;
    return __uint_as_float(u);
}

// ---- packed f32x2 ops (full-rate fp32 on sm_103a) ----
__device__ __forceinline__ void fma2(ull& d, ull a, ull b) {
    asm("fma.rn.f32x2 %0, %1, %2, %0;" : "+l"(d) : "l"(a), "l"(b));
}
__device__ __forceinline__ ull pack2(float lo, float hi) {
    ull r; asm("mov.b64 %0, {%1, %2};" : "=l"(r) : "f"(lo), "f"(hi)); return r;
}
__device__ __forceinline__ float unpack_sum(ull a) {
    float lo = __uint_as_float((unsigned)a);
    float hi = __uint_as_float((unsigned)(a >> 32));
    return lo + hi;
}

// load 8 strided channels and pack into 4 f32x2 regs
__device__ __forceinline__ void load8(const float* __restrict__ fb, int cc, ull* r) {
    float f0 = fb[(cc+0)*NPTS], f1 = fb[(cc+1)*NPTS];
    float f2 = fb[(cc+2)*NPTS], f3 = fb[(cc+3)*NPTS];
    float f4 = fb[(cc+4)*NPTS], f5 = fb[(cc+5)*NPTS];
    float f6 = fb[(cc+6)*NPTS], f7 = fb[(cc+7)*NPTS];
    r[0] = pack2(f0, f1); r[1] = pack2(f2, f3);
    r[2] = pack2(f4, f5); r[3] = pack2(f6, f7);
}

// ---------------------------------------------------------------- zero scratch
__global__ void k_zero() {
    int i = blockIdx.x * blockDim.x + threadIdx.x;
    if (i < NPROT*C_DIM) g_num[i]  = 0.f;
    if (i < NPROT)       g_cnt[i]  = 0.f;
    if (i < 3*MBG)       g_akey[i] = 0ull;
    if (i < MQ*NCLS)     g_qkey[i] = 0u;
    if (i < 3)           g_ccnt[i] = 0;
}

// ---------------- ordered seed scan: first KP masked indices per partition
__global__ void __launch_bounds__(256) k_seedscan(const int* __restrict__ sy) {
    int p = blockIdx.x;
    int M = (p == 2) ? MBG : MFG;
    __shared__ int wsum[8];
    __shared__ int sbase;
    int tid = threadIdx.x, lane = tid & 31, w = tid >> 5;
    if (tid == 0) sbase = 0;
    __syncthreads();
    for (int base = 0; base < M; base += 256) {
        int idx = base + tid;
        int b = 0;
        if (idx < M) b = (p == 2) ? (sy[idx] == 0) : (sy[p*MFG + idx] != 0);
        unsigned bal = __ballot_sync(0xFFFFFFFFu, b);
        int lp = __popc(bal & ((1u << lane) - 1u));
        if (lane == 0) wsum[w] = __popc(bal);
        __syncthreads();
        int off = 0;
        for (int i = 0; i < w; i++) off += wsum[i];
        int pos = sbase + off + lp;
        if (b && pos < KP) g_seed_idx[p*KP + pos] = idx;
        __syncthreads();
        if (tid == 0) { int t = 0; for (int i = 0; i < 8; i++) t += wsum[i]; sbase += t; }
        __syncthreads();
        if (sbase >= KP) break;
    }
}

// ------------- parallel unordered compaction (order irrelevant for matching)
__global__ void __launch_bounds__(256) k_compact(const int* __restrict__ sy) {
    int p = blockIdx.y;
    int M = (p == 2) ? MBG : MFG;
    int idx = blockIdx.x * 256 + threadIdx.x;
    int b = (idx < M) ? ((p == 2) ? (sy[idx] == 0) : (sy[p*MFG + idx] != 0)) : 0;
    unsigned bal = __ballot_sync(0xFFFFFFFFu, b);
    int lane = threadIdx.x & 31;
    int lp = __popc(bal & ((1u << lane) - 1u));
    int base = 0;
    if (lane == 0 && bal) base = atomicAdd(&g_ccnt[p], __popc(bal));
    base = __shfl_sync(0xFFFFFFFFu, base, 0);
    if (b) g_cidx[p*MBG + base + lp] = idx;
}

// ------------------------------------------------ gather + normalize seeds
__global__ void k_norm_seeds(const float* __restrict__ sf) {
    int g = blockIdx.x;              // 0..299
    int p = g / KP;
    int idx = g_seed_idx[g];
    int grp = (p == 2) ? (idx >> 11) : (p*KSHOT + (idx >> 11));
    const float* fb = sf + (size_t)grp*SHOT_STRIDE + (idx & 2047);
    int c = threadIdx.x;             // 320 threads
    float v = fb[c * NPTS];
    __shared__ float red[16];
    __shared__ float stot;
    float s = v * v;
    #pragma unroll
    for (int o = 16; o; o >>= 1) s += __shfl_down_sync(0xFFFFFFFFu, s, o);
    if ((c & 31) == 0) red[c >> 5] = s;
    __syncthreads();
    if (c == 0) { float t = 0.f; for (int i = 0; i < C_DIM/32; i++) t += red[i]; stot = t; }
    __syncthreads();
    g_seeds[g*C_DIM + c] = v / (sqrtf(stot) + 1e-8f);
}

// ---- match: 4 points/thread x 10-seed tile, register-tiled f32x2 GEMM
__global__ void __launch_bounds__(128) k_match(const float* __restrict__ sf) {
    __shared__ __align__(16) float s[TJM*C_DIM];
    int p = blockIdx.z, t = blockIdx.y;
    int cnt = g_ccnt[p];
    int i0 = blockIdx.x * (128*PTS);
    if (i0 >= cnt) return;
    const float* sp = g_seeds + (size_t)(p*KP + t*TJM)*C_DIM;
    for (int i = threadIdx.x; i < TJM*C_DIM; i += 128) s[i] = sp[i];
    __syncthreads();

    const float* fbp[PTS];
    bool valid[PTS];
    int ipt[PTS];
    #pragma unroll
    for (int k = 0; k < PTS; k++) {
        int i = i0 + threadIdx.x + 128*k;
        valid[k] = (i < cnt);
        ipt[k] = i;
        int ii = valid[k] ? i : (cnt - 1);
        int idx = g_cidx[p*MBG + ii];
        int grp = (p == 2) ? (idx >> 11) : (p*KSHOT + (idx >> 11));
        fbp[k] = sf + (size_t)grp*SHOT_STRIDE + (idx & 2047);
    }

    ull acc[PTS][TJM];
    #pragma unroll
    for (int k = 0; k < PTS; k++)
        #pragma unroll
        for (int j = 0; j < TJM; j++) acc[k][j] = 0ull;

    for (int cc = 0; cc < C_DIM; cc += 8) {
        ull A[PTS][4];
        #pragma unroll
        for (int k = 0; k < PTS; k++) load8(fbp[k], cc, A[k]);
        #pragma unroll
        for (int j = 0; j < TJM; j++) {
            ulonglong2 s01 = *(const ulonglong2*)&s[j*C_DIM + cc];
            ulonglong2 s23 = *(const ulonglong2*)&s[j*C_DIM + cc + 4];
            #pragma unroll
            for (int k = 0; k < PTS; k++) {
                fma2(acc[k][j], A[k][0], s01.x);
                fma2(acc[k][j], A[k][1], s01.y);
                fma2(acc[k][j], A[k][2], s23.x);
                fma2(acc[k][j], A[k][3], s23.y);
            }
        }
    }

    #pragma unroll
    for (int k = 0; k < PTS; k++) {
        if (!valid[k]) continue;
        float best = unpack_sum(acc[k][0]); int bj = 0;
        #pragma unroll
        for (int j = 1; j < TJM; j++) {
            float d = unpack_sum(acc[k][j]);
            if (d > best) { best = d; bj = j; }
        }
        ull key = ((ull)fkey(best) << 32) | (ull)(0xFFFFFFFFu - (unsigned)(t*TJM + bj));
        atomicMax(&g_akey[p*MBG + ipt[k]], key);
    }
}

// ------------- accumulate cluster sums (4-way channel split for parallelism)
__global__ void __launch_bounds__(128) k_accum(const float* __restrict__ sf) {
    int p = blockIdx.z;
    int cslice = blockIdx.y;                  // 0..3, 80 channels each
    int cnt = g_ccnt[p];
    int i = blockIdx.x * 128 + threadIdx.x;
    if (i >= cnt) return;
    int idx = g_cidx[p*MBG + i];
    int grp = (p == 2) ? (idx >> 11) : (p*KSHOT + (idx >> 11));
    const float* fb = sf + (size_t)grp*SHOT_STRIDE + (idx & 2047);
    unsigned j = 0xFFFFFFFFu - (unsigned)(g_akey[p*MBG + i] & 0xFFFFFFFFull);
    int proto = p*KP + (int)j;
    if (cslice == 0) atomicAdd(&g_cnt[proto], 1.0f);
    float* dst = g_num + (size_t)proto*C_DIM;
    int c0 = cslice * 80;
    #pragma unroll 4
    for (int c = c0; c < c0 + 80; c++) atomicAdd(&dst[c], fb[c*NPTS]);
}

// ------------------------------------------------ finalize + normalize protos
__global__ void k_norm_protos() {
    int g = blockIdx.x;
    int c = threadIdx.x;             // 320 threads
    float den = g_cnt[g] + 1e-8f;
    float v = g_num[g*C_DIM + c] / den;
    __shared__ float red[16];
    __shared__ float stot;
    float s = v * v;
    #pragma unroll
    for (int o = 16; o; o >>= 1) s += __shfl_down_sync(0xFFFFFFFFu, s, o);
    if ((c & 31) == 0) red[c >> 5] = s;
    __syncthreads();
    if (c == 0) { float t = 0.f; for (int i = 0; i < C_DIM/32; i++) t += red[i]; stot = t; }
    __syncthreads();
    g_protos[g*C_DIM + c] = v / (sqrtf(stot) + 1e-8f);
}

// ---- query match: 4 points/thread x 10-proto tile + fused norm (t==0)
// proto groups: [0..99]=fg class 1, [100..199]=fg class 2, [200..299]=bg cls 0
__global__ void __launch_bounds__(128) k_qmatch(const float* __restrict__ qf) {
    __shared__ __align__(16) float s[TJM*C_DIM];
    int t = blockIdx.y;                       // 0..29
    int pg = t / (KP/TJM);
    int cls = (pg == 2) ? 0 : pg + 1;
    const float* sp = g_protos + (size_t)t*TJM*C_DIM;
    for (int i = threadIdx.x; i < TJM*C_DIM; i += 128) s[i] = sp[i];
    __syncthreads();

    int m0 = blockIdx.x * (128*PTS);
    const float* fbp[PTS];
    int mpt[PTS];
    #pragma unroll
    for (int k = 0; k < PTS; k++) {
        int m = m0 + threadIdx.x + 128*k;
        mpt[k] = m;
        int q = m >> 11, n = m & 2047;
        fbp[k] = qf + (size_t)q*SHOT_STRIDE + n;
    }

    ull acc[PTS][TJM];
    #pragma unroll
    for (int k = 0; k < PTS; k++)
        #pragma unroll
        for (int j = 0; j < TJM; j++) acc[k][j] = 0ull;
    ull q2p[PTS];
    #pragma unroll
    for (int k = 0; k < PTS; k++) q2p[k] = 0ull;
    bool do_norm = (t == 0);

    for (int cc = 0; cc < C_DIM; cc += 8) {
        ull A[PTS][4];
        #pragma unroll
        for (int k = 0; k < PTS; k++) load8(fbp[k], cc, A[k]);
        #pragma unroll
        for (int j = 0; j < TJM; j++) {
            ulonglong2 s01 = *(const ulonglong2*)&s[j*C_DIM + cc];
            ulonglong2 s23 = *(const ulonglong2*)&s[j*C_DIM + cc + 4];
            #pragma unroll
            for (int k = 0; k < PTS; k++) {
                fma2(acc[k][j], A[k][0], s01.x);
                fma2(acc[k][j], A[k][1], s01.y);
                fma2(acc[k][j], A[k][2], s23.x);
                fma2(acc[k][j], A[k][3], s23.y);
            }
        }
        if (do_norm) {
            #pragma unroll
            for (int k = 0; k < PTS; k++) {
                fma2(q2p[k], A[k][0], A[k][0]); fma2(q2p[k], A[k][1], A[k][1]);
                fma2(q2p[k], A[k][2], A[k][2]); fma2(q2p[k], A[k][3], A[k][3]);
            }
        }
    }
    #pragma unroll
    for (int k = 0; k < PTS; k++) {
        if (do_norm) {
            float q2 = unpack_sum(q2p[k]);
            g_qinv[mpt[k]] = 1.f / (sqrtf(q2) + 1e-8f);
        }
        float mx = unpack_sum(acc[k][0]);
        #pragma unroll
        for (int j = 1; j < TJM; j++) mx = fmaxf(mx, unpack_sum(acc[k][j]));
        atomicMax(&g_qkey[mpt[k]*NCLS + cls], fkey(mx));
    }
}

// ------------------- loss, query_pred out, mean-threshold, final labels
__global__ void __launch_bounds__(1024) k_finalize(const int* __restrict__ qy,
                                                   float* __restrict__ out) {
    __shared__ float sconf[MQ];
    __shared__ signed char sarg[MQ];
    __shared__ float red[1024];
    int tid = threadIdx.x;
    float lsum = 0.f, csum = 0.f;
    #pragma unroll
    for (int r = 0; r < MQ/1024; r++) {
        int m = tid + r*1024;
        int q = m >> 11, n = m & 2047;
        float inv = g_qinv[m];
        float p0 = fdec(g_qkey[m*NCLS + 0]) * inv;
        float p1 = fdec(g_qkey[m*NCLS + 1]) * inv;
        float p2 = fdec(g_qkey[m*NCLS + 2]) * inv;
        out[1 + (size_t)(q*NCLS + 0)*NPTS + n] = p0;
        out[1 + (size_t)(q*NCLS + 1)*NPTS + n] = p1;
        out[1 + (size_t)(q*NCLS + 2)*NPTS + n] = p2;
        float mx = p0; int a = 0;
        if (p1 > mx) { mx = p1; a = 1; }
        if (p2 > mx) { mx = p2; a = 2; }
        float lse = mx + logf(expf(p0 - mx) + expf(p1 - mx) + expf(p2 - mx));
        int lab = qy[m];
        float pl = (lab == 0) ? p0 : ((lab == 1) ? p1 : p2);
        lsum += lse - pl;
        sconf[m] = mx;
        sarg[m]  = (signed char)a;
        csum += mx;
    }
    red[tid] = lsum; __syncthreads();
    for (int o = 512; o; o >>= 1) { if (tid < o) red[tid] += red[tid + o]; __syncthreads(); }
    float tot_l = red[0];
    __syncthreads();
    red[tid] = csum; __syncthreads();
    for (int o = 512; o; o >>= 1) { if (tid < o) red[tid] += red[tid + o]; __syncthreads(); }
    float mean_c = red[0] / (float)MQ;
    if (tid == 0) out[0] = 2.f * tot_l / (float)MQ;
    #pragma unroll
    for (int r = 0; r < MQ/1024; r++) {
        int m = tid + r*1024;
        out[1 + (size_t)NQ*NCLS*NPTS + m] = (sconf[m] > mean_c) ? (float)sarg[m] : -1.f;
    }
}

// ---------------------------------------------------------------------- launch
extern "C" void kernel_launch(void* const* d_in, const int* in_sizes, int n_in,
                              void* d_out, int out_size) {
    const float* sf = (const float*)d_in[0];   // support_feat [2,5,320,2048]
    const float* qf = (const float*)d_in[1];   // query_feat   [2,320,2048]
    const int*   sy = (const int*)  d_in[2];   // support_y    [2,5,2048]
    const int*   qy = (const int*)  d_in[3];   // query_y      [2,2048]
    float* out = (float*)d_out;                // [1 + 12288 + 4096]

    k_zero<<<(NPROT*C_DIM + 255)/256, 256>>>();
    k_seedscan<<<3, 256>>>(sy);
    k_compact<<<dim3(MBG/256, 3), 256>>>(sy);
    k_norm_seeds<<<NPROT, C_DIM>>>(sf);
    k_match<<<dim3(MBG/(128*PTS), KP/TJM, 3), 128>>>(sf);
    k_accum<<<dim3(MBG/128, 4, 3), 128>>>(sf);
    k_norm_protos<<<NPROT, C_DIM>>>();
    k_qmatch<<<dim3(MQ/(128*PTS), NPROT/TJM), 128>>>(qf);
    k_finalize<<<1, 1024>>>(qy, out);
}

// round 17
// speedup vs baseline: 1.7789x; 1.3853x over previous
#include <cuda_runtime.h>
#include <math.h>

// Problem constants
#define C_DIM 320
#define NPTS  2048
#define NWAY  2
#define KSHOT 5
#define KP    100
#define NCLS  3
#define NQ    2
#define MFG   (KSHOT*NPTS)           // 10240
#define MBG   (NWAY*KSHOT*NPTS)      // 20480
#define SHOT_STRIDE (C_DIM*NPTS)     // 655360
#define TJM   10                     // seeds per tile
#define PTS   4                      // points per thread
#define NPROT (NCLS*KP)              // 300
#define MQ    (NQ*NPTS)              // 4096

typedef unsigned long long ull;

// Scratch (device globals — no allocation allowed)
__device__ int    g_seed_idx[NPROT];
__device__ int    g_cidx[3*MBG];
__device__ int    g_ccnt[3];
__device__ __align__(16) float g_seeds [NPROT*C_DIM];
__device__ __align__(16) float g_num   [NPROT*C_DIM];
__device__ float  g_cnt   [NPROT];
__device__ __align__(16) float g_protos[NPROT*C_DIM];
__device__ ull    g_akey  [3*MBG];
__device__ unsigned int g_qkey[MQ*NCLS];
__device__ float  g_qinv  [MQ];

// ---- monotonic float <-> uint key encoding ----
__device__ __forceinline__ unsigned fkey(float v) {
    unsigned u = __float_as_uint(v);
    return (u & 0x80000000u) ? ~u : (u | 0x80000000u);
}
__device__ __forceinline__ float fdec(unsigned k) {
    unsigned u = (k & 0x80000000u) ? (k ^ 0x80000000u) : ~k;
    return __uint_as_float(u);
}

// ---- packed f32x2 ops (full-rate fp32 on sm_103a) ----
__device__ __forceinline__ void fma2(ull& d, ull a, ull b) {
    asm("fma.rn.f32x2 %0, %1, %2, %0;" : "+l"(d) : "l"(a), "l"(b));
}
__device__ __forceinline__ ull pack2(float lo, float hi) {
    ull r; asm("mov.b64 %0, {%1, %2};" : "=l"(r) : "f"(lo), "f"(hi)); return r;
}
__device__ __forceinline__ float unpack_sum(ull a) {
    float lo = __uint_as_float((unsigned)a);
    float hi = __uint_as_float((unsigned)(a >> 32));
    return lo + hi;
}

// vectorized global reduction: one red.global.add.v4.f32 per 4 channels
__device__ __forceinline__ void red_add_v4(float* p, float a, float b, float c, float d) {
    asm volatile("red.global.add.v4.f32 [%0], {%1, %2, %3, %4};"
                 :: "l"(p), "f"(a), "f"(b), "f"(c), "f"(d) : "memory");
}

// load 8 strided channels and pack into 4 f32x2 regs
__device__ __forceinline__ void load8(const float* __restrict__ fb, int cc, ull* r) {
    float f0 = fb[(cc+0)*NPTS], f1 = fb[(cc+1)*NPTS];
    float f2 = fb[(cc+2)*NPTS], f3 = fb[(cc+3)*NPTS];
    float f4 = fb[(cc+4)*NPTS], f5 = fb[(cc+5)*NPTS];
    float f6 = fb[(cc+6)*NPTS], f7 = fb[(cc+7)*NPTS];
    r[0] = pack2(f0, f1); r[1] = pack2(f2, f3);
    r[2] = pack2(f4, f5); r[3] = pack2(f6, f7);
}

// ---------------------------------------------------------------- zero scratch
__global__ void k_zero() {
    int i = blockIdx.x * blockDim.x + threadIdx.x;
    if (i < NPROT*C_DIM) g_num[i]  = 0.f;
    if (i < NPROT)       g_cnt[i]  = 0.f;
    if (i < 3*MBG)       g_akey[i] = 0ull;
    if (i < MQ*NCLS)     g_qkey[i] = 0u;
    if (i < 3)           g_ccnt[i] = 0;
}

// ---------------- ordered seed scan: first KP masked indices per partition
__global__ void __launch_bounds__(256) k_seedscan(const int* __restrict__ sy) {
    int p = blockIdx.x;
    int M = (p == 2) ? MBG : MFG;
    __shared__ int wsum[8];
    __shared__ int sbase;
    int tid = threadIdx.x, lane = tid & 31, w = tid >> 5;
    if (tid == 0) sbase = 0;
    __syncthreads();
    for (int base = 0; base < M; base += 256) {
        int idx = base + tid;
        int b = 0;
        if (idx < M) b = (p == 2) ? (sy[idx] == 0) : (sy[p*MFG + idx] != 0);
        unsigned bal = __ballot_sync(0xFFFFFFFFu, b);
        int lp = __popc(bal & ((1u << lane) - 1u));
        if (lane == 0) wsum[w] = __popc(bal);
        __syncthreads();
        int off = 0;
        for (int i = 0; i < w; i++) off += wsum[i];
        int pos = sbase + off + lp;
        if (b && pos < KP) g_seed_idx[p*KP + pos] = idx;
        __syncthreads();
        if (tid == 0) { int t = 0; for (int i = 0; i < 8; i++) t += wsum[i]; sbase += t; }
        __syncthreads();
        if (sbase >= KP) break;
    }
}

// ------------- parallel unordered compaction (order irrelevant for matching)
__global__ void __launch_bounds__(256) k_compact(const int* __restrict__ sy) {
    int p = blockIdx.y;
    int M = (p == 2) ? MBG : MFG;
    int idx = blockIdx.x * 256 + threadIdx.x;
    int b = (idx < M) ? ((p == 2) ? (sy[idx] == 0) : (sy[p*MFG + idx] != 0)) : 0;
    unsigned bal = __ballot_sync(0xFFFFFFFFu, b);
    int lane = threadIdx.x & 31;
    int lp = __popc(bal & ((1u << lane) - 1u));
    int base = 0;
    if (lane == 0 && bal) base = atomicAdd(&g_ccnt[p], __popc(bal));
    base = __shfl_sync(0xFFFFFFFFu, base, 0);
    if (b) g_cidx[p*MBG + base + lp] = idx;
}

// ------------------------------------------------ gather + normalize seeds
__global__ void k_norm_seeds(const float* __restrict__ sf) {
    int g = blockIdx.x;              // 0..299
    int p = g / KP;
    int idx = g_seed_idx[g];
    int grp = (p == 2) ? (idx >> 11) : (p*KSHOT + (idx >> 11));
    const float* fb = sf + (size_t)grp*SHOT_STRIDE + (idx & 2047);
    int c = threadIdx.x;             // 320 threads
    float v = fb[c * NPTS];
    __shared__ float red[16];
    __shared__ float stot;
    float s = v * v;
    #pragma unroll
    for (int o = 16; o; o >>= 1) s += __shfl_down_sync(0xFFFFFFFFu, s, o);
    if ((c & 31) == 0) red[c >> 5] = s;
    __syncthreads();
    if (c == 0) { float t = 0.f; for (int i = 0; i < C_DIM/32; i++) t += red[i]; stot = t; }
    __syncthreads();
    g_seeds[g*C_DIM + c] = v / (sqrtf(stot) + 1e-8f);
}

// ---- match: 4 points/thread x 10-seed tile, register-tiled f32x2 GEMM
__global__ void __launch_bounds__(128) k_match(const float* __restrict__ sf) {
    __shared__ __align__(16) float s[TJM*C_DIM];
    int p = blockIdx.z, t = blockIdx.y;
    int cnt = g_ccnt[p];
    int i0 = blockIdx.x * (128*PTS);
    if (i0 >= cnt) return;
    const float* sp = g_seeds + (size_t)(p*KP + t*TJM)*C_DIM;
    for (int i = threadIdx.x; i < TJM*C_DIM; i += 128) s[i] = sp[i];
    __syncthreads();

    const float* fbp[PTS];
    bool valid[PTS];
    int ipt[PTS];
    #pragma unroll
    for (int k = 0; k < PTS; k++) {
        int i = i0 + threadIdx.x + 128*k;
        valid[k] = (i < cnt);
        ipt[k] = i;
        int ii = valid[k] ? i : (cnt - 1);
        int idx = g_cidx[p*MBG + ii];
        int grp = (p == 2) ? (idx >> 11) : (p*KSHOT + (idx >> 11));
        fbp[k] = sf + (size_t)grp*SHOT_STRIDE + (idx & 2047);
    }

    ull acc[PTS][TJM];
    #pragma unroll
    for (int k = 0; k < PTS; k++)
        #pragma unroll
        for (int j = 0; j < TJM; j++) acc[k][j] = 0ull;

    for (int cc = 0; cc < C_DIM; cc += 8) {
        ull A[PTS][4];
        #pragma unroll
        for (int k = 0; k < PTS; k++) load8(fbp[k], cc, A[k]);
        #pragma unroll
        for (int j = 0; j < TJM; j++) {
            ulonglong2 s01 = *(const ulonglong2*)&s[j*C_DIM + cc];
            ulonglong2 s23 = *(const ulonglong2*)&s[j*C_DIM + cc + 4];
            #pragma unroll
            for (int k = 0; k < PTS; k++) {
                fma2(acc[k][j], A[k][0], s01.x);
                fma2(acc[k][j], A[k][1], s01.y);
                fma2(acc[k][j], A[k][2], s23.x);
                fma2(acc[k][j], A[k][3], s23.y);
            }
        }
    }

    #pragma unroll
    for (int k = 0; k < PTS; k++) {
        if (!valid[k]) continue;
        float best = unpack_sum(acc[k][0]); int bj = 0;
        #pragma unroll
        for (int j = 1; j < TJM; j++) {
            float d = unpack_sum(acc[k][j]);
            if (d > best) { best = d; bj = j; }
        }
        ull key = ((ull)fkey(best) << 32) | (ull)(0xFFFFFFFFu - (unsigned)(t*TJM + bj));
        atomicMax(&g_akey[p*MBG + ipt[k]], key);
    }
}

// ------ accumulate cluster sums: vectorized red.global.add.v4.f32 scatter
__global__ void __launch_bounds__(128) k_accum(const float* __restrict__ sf) {
    int p = blockIdx.z;
    int cslice = blockIdx.y;                  // 0..3, 80 channels each
    int cnt = g_ccnt[p];
    int i = blockIdx.x * 128 + threadIdx.x;
    if (i >= cnt) return;
    int idx = g_cidx[p*MBG + i];
    int grp = (p == 2) ? (idx >> 11) : (p*KSHOT + (idx >> 11));
    const float* fb = sf + (size_t)grp*SHOT_STRIDE + (idx & 2047);
    unsigned j = 0xFFFFFFFFu - (unsigned)(g_akey[p*MBG + i] & 0xFFFFFFFFull);
    int proto = p*KP + (int)j;
    if (cslice == 0) atomicAdd(&g_cnt[proto], 1.0f);
    float* dst = g_num + (size_t)proto*C_DIM;
    int c0 = cslice * 80;
    #pragma unroll 4
    for (int c = c0; c < c0 + 80; c += 4) {
        float v0 = fb[(c+0)*NPTS], v1 = fb[(c+1)*NPTS];
        float v2 = fb[(c+2)*NPTS], v3 = fb[(c+3)*NPTS];
        red_add_v4(&dst[c], v0, v1, v2, v3);
    }
}

// ------------------------------------------------ finalize + normalize protos
__global__ void k_norm_protos() {
    int g = blockIdx.x;
    int c = threadIdx.x;             // 320 threads
    float den = g_cnt[g] + 1e-8f;
    float v = g_num[g*C_DIM + c] / den;
    __shared__ float red[16];
    __shared__ float stot;
    float s = v * v;
    #pragma unroll
    for (int o = 16; o; o >>= 1) s += __shfl_down_sync(0xFFFFFFFFu, s, o);
    if ((c & 31) == 0) red[c >> 5] = s;
    __syncthreads();
    if (c == 0) { float t = 0.f; for (int i = 0; i < C_DIM/32; i++) t += red[i]; stot = t; }
    __syncthreads();
    g_protos[g*C_DIM + c] = v / (sqrtf(stot) + 1e-8f);
}

// ---- query match: 4 points/thread x 10-proto tile + fused norm (t==0)
// proto groups: [0..99]=fg class 1, [100..199]=fg class 2, [200..299]=bg cls 0
__global__ void __launch_bounds__(128) k_qmatch(const float* __restrict__ qf) {
    __shared__ __align__(16) float s[TJM*C_DIM];
    int t = blockIdx.y;                       // 0..29
    int pg = t / (KP/TJM);
    int cls = (pg == 2) ? 0 : pg + 1;
    const float* sp = g_protos + (size_t)t*TJM*C_DIM;
    for (int i = threadIdx.x; i < TJM*C_DIM; i += 128) s[i] = sp[i];
    __syncthreads();

    int m0 = blockIdx.x * (128*PTS);
    const float* fbp[PTS];
    int mpt[PTS];
    #pragma unroll
    for (int k = 0; k < PTS; k++) {
        int m = m0 + threadIdx.x + 128*k;
        mpt[k] = m;
        int q = m >> 11, n = m & 2047;
        fbp[k] = qf + (size_t)q*SHOT_STRIDE + n;
    }

    ull acc[PTS][TJM];
    #pragma unroll
    for (int k = 0; k < PTS; k++)
        #pragma unroll
        for (int j = 0; j < TJM; j++) acc[k][j] = 0ull;
    ull q2p[PTS];
    #pragma unroll
    for (int k = 0; k < PTS; k++) q2p[k] = 0ull;
    bool do_norm = (t == 0);

    for (int cc = 0; cc < C_DIM; cc += 8) {
        ull A[PTS][4];
        #pragma unroll
        for (int k = 0; k < PTS; k++) load8(fbp[k], cc, A[k]);
        #pragma unroll
        for (int j = 0; j < TJM; j++) {
            ulonglong2 s01 = *(const ulonglong2*)&s[j*C_DIM + cc];
            ulonglong2 s23 = *(const ulonglong2*)&s[j*C_DIM + cc + 4];
            #pragma unroll
            for (int k = 0; k < PTS; k++) {
                fma2(acc[k][j], A[k][0], s01.x);
                fma2(acc[k][j], A[k][1], s01.y);
                fma2(acc[k][j], A[k][2], s23.x);
                fma2(acc[k][j], A[k][3], s23.y);
            }
        }
        if (do_norm) {
            #pragma unroll
            for (int k = 0; k < PTS; k++) {
                fma2(q2p[k], A[k][0], A[k][0]); fma2(q2p[k], A[k][1], A[k][1]);
                fma2(q2p[k], A[k][2], A[k][2]); fma2(q2p[k], A[k][3], A[k][3]);
            }
        }
    }
    #pragma unroll
    for (int k = 0; k < PTS; k++) {
        if (do_norm) {
            float q2 = unpack_sum(q2p[k]);
            g_qinv[mpt[k]] = 1.f / (sqrtf(q2) + 1e-8f);
        }
        float mx = unpack_sum(acc[k][0]);
        #pragma unroll
        for (int j = 1; j < TJM; j++) mx = fmaxf(mx, unpack_sum(acc[k][j]));
        atomicMax(&g_qkey[mpt[k]*NCLS + cls], fkey(mx));
    }
}

// ------------------- loss, query_pred out, mean-threshold, final labels
__global__ void __launch_bounds__(1024) k_finalize(const int* __restrict__ qy,
                                                   float* __restrict__ out) {
    __shared__ float sconf[MQ];
    __shared__ signed char sarg[MQ];
    __shared__ float red[1024];
    int tid = threadIdx.x;
    float lsum = 0.f, csum = 0.f;
    #pragma unroll
    for (int r = 0; r < MQ/1024; r++) {
        int m = tid + r*1024;
        int q = m >> 11, n = m & 2047;
        float inv = g_qinv[m];
        float p0 = fdec(g_qkey[m*NCLS + 0]) * inv;
        float p1 = fdec(g_qkey[m*NCLS + 1]) * inv;
        float p2 = fdec(g_qkey[m*NCLS + 2]) * inv;
        out[1 + (size_t)(q*NCLS + 0)*NPTS + n] = p0;
        out[1 + (size_t)(q*NCLS + 1)*NPTS + n] = p1;
        out[1 + (size_t)(q*NCLS + 2)*NPTS + n] = p2;
        float mx = p0; int a = 0;
        if (p1 > mx) { mx = p1; a = 1; }
        if (p2 > mx) { mx = p2; a = 2; }
        float lse = mx + logf(expf(p0 - mx) + expf(p1 - mx) + expf(p2 - mx));
        int lab = qy[m];
        float pl = (lab == 0) ? p0 : ((lab == 1) ? p1 : p2);
        lsum += lse - pl;
        sconf[m] = mx;
        sarg[m]  = (signed char)a;
        csum += mx;
    }
    red[tid] = lsum; __syncthreads();
    for (int o = 512; o; o >>= 1) { if (tid < o) red[tid] += red[tid + o]; __syncthreads(); }
    float tot_l = red[0];
    __syncthreads();
    red[tid] = csum; __syncthreads();
    for (int o = 512; o; o >>= 1) { if (tid < o) red[tid] += red[tid + o]; __syncthreads(); }
    float mean_c = red[0] / (float)MQ;
    if (tid == 0) out[0] = 2.f * tot_l / (float)MQ;
    #pragma unroll
    for (int r = 0; r < MQ/1024; r++) {
        int m = tid + r*1024;
        out[1 + (size_t)NQ*NCLS*NPTS + m] = (sconf[m] > mean_c) ? (float)sarg[m] : -1.f;
    }
}

// ---------------------------------------------------------------------- launch
extern "C" void kernel_launch(void* const* d_in, const int* in_sizes, int n_in,
                              void* d_out, int out_size) {
    const float* sf = (const float*)d_in[0];   // support_feat [2,5,320,2048]
    const float* qf = (const float*)d_in[1];   // query_feat   [2,320,2048]
    const int*   sy = (const int*)  d_in[2];   // support_y    [2,5,2048]
    const int*   qy = (const int*)  d_in[3];   // query_y      [2,2048]
    float* out = (float*)d_out;                // [1 + 12288 + 4096]

    k_zero<<<(NPROT*C_DIM + 255)/256, 256>>>();
    k_seedscan<<<3, 256>>>(sy);
    k_compact<<<dim3(MBG/256, 3), 256>>>(sy);
    k_norm_seeds<<<NPROT, C_DIM>>>(sf);
    k_match<<<dim3(MBG/(128*PTS), KP/TJM, 3), 128>>>(sf);
    k_accum<<<dim3(MBG/128, 4, 3), 128>>>(sf);
    k_norm_protos<<<NPROT, C_DIM>>>();
    k_qmatch<<<dim3(MQ/(128*PTS), NPROT/TJM), 128>>>(qf);
    k_finalize<<<1, 1024>>>(qy, out);
}